// round 1
// baseline (speedup 1.0000x reference)
#include <cuda_runtime.h>

#define BATCH   4
#define NPTS    8192
#define THREADS 256
#define IX      2
#define TILES   (NPTS / (THREADS * IX))   // 16 query tiles per (batch, direction)

// d_out is poisoned to 0xAA; zero it before accumulation.
__global__ void zero_out_kernel(float* out) { *out = 0.0f; }

// One block = (batch b, direction dir, query tile). Stages ALL 8192 targets of
// (b, dir) into shared memory as float4 (tx, ty, tz, ||t||^2), then each thread
// computes min over all targets of (||t||^2 - 2 q·t) for IX queries, adds ||q||^2,
// clamps at 0, and block-reduces into a single atomicAdd.
__global__ __launch_bounds__(THREADS) void chamfer_kernel(
    const float* __restrict__ x, const float* __restrict__ y,
    float* __restrict__ out)
{
    extern __shared__ float4 sT[];  // NPTS float4 = 128 KB

    const int bid  = blockIdx.x;
    const int tile = bid % TILES;
    const int dir  = (bid / TILES) & 1;
    const int b    = bid / (TILES * 2);

    const float* q = (dir ? y : x) + (size_t)b * NPTS * 3;
    const float* t = (dir ? x : y) + (size_t)b * NPTS * 3;

    // Stage targets with precomputed squared norm.
    for (int j = threadIdx.x; j < NPTS; j += THREADS) {
        float tx = t[3 * j + 0];
        float ty = t[3 * j + 1];
        float tz = t[3 * j + 2];
        sT[j] = make_float4(tx, ty, tz, fmaf(tx, tx, fmaf(ty, ty, tz * tz)));
    }
    __syncthreads();

    // Two queries per thread.
    const int q0 = tile * (THREADS * IX) + threadIdx.x;
    const int q1 = q0 + THREADS;

    const float qx0 = q[3 * q0 + 0], qy0 = q[3 * q0 + 1], qz0 = q[3 * q0 + 2];
    const float qx1 = q[3 * q1 + 0], qy1 = q[3 * q1 + 1], qz1 = q[3 * q1 + 2];

    const float w0 = fmaf(qx0, qx0, fmaf(qy0, qy0, qz0 * qz0));
    const float w1 = fmaf(qx1, qx1, fmaf(qy1, qy1, qz1 * qz1));

    // Pre-scale by -2 so inner loop is pure FMA: v = T.w - 2 q·T
    const float ax0 = -2.0f * qx0, ay0 = -2.0f * qy0, az0 = -2.0f * qz0;
    const float ax1 = -2.0f * qx1, ay1 = -2.0f * qy1, az1 = -2.0f * qz1;

    float m0 = 3.402823466e+38f;
    float m1 = 3.402823466e+38f;

#pragma unroll 8
    for (int j = 0; j < NPTS; ++j) {
        const float4 T = sT[j];   // warp-broadcast LDS.128
        const float v0 = fmaf(ax0, T.x, fmaf(ay0, T.y, fmaf(az0, T.z, T.w)));
        const float v1 = fmaf(ax1, T.x, fmaf(ay1, T.y, fmaf(az1, T.z, T.w)));
        m0 = fminf(m0, v0);
        m1 = fminf(m1, v1);
    }

    float s = fmaxf(m0 + w0, 0.0f) + fmaxf(m1 + w1, 0.0f);

    // Warp reduction then cross-warp reduction.
#pragma unroll
    for (int o = 16; o > 0; o >>= 1)
        s += __shfl_xor_sync(0xffffffffu, s, o);

    __shared__ float red[THREADS / 32];
    if ((threadIdx.x & 31) == 0) red[threadIdx.x >> 5] = s;
    __syncthreads();

    if (threadIdx.x < THREADS / 32) {
        s = red[threadIdx.x];
#pragma unroll
        for (int o = (THREADS / 32) / 2; o > 0; o >>= 1)
            s += __shfl_xor_sync(0xffu, s, o);
        if (threadIdx.x == 0) {
            // final = sum of all clamped mins / (BATCH * NPTS)
            atomicAdd(out, s * (1.0f / (float)(BATCH * NPTS)));
        }
    }
}

extern "C" void kernel_launch(void* const* d_in, const int* in_sizes, int n_in,
                              void* d_out, int out_size)
{
    (void)in_sizes; (void)n_in; (void)out_size;
    const float* x = (const float*)d_in[0];
    const float* y = (const float*)d_in[1];
    float* out = (float*)d_out;

    zero_out_kernel<<<1, 1>>>(out);

    const int smem = NPTS * (int)sizeof(float4);  // 131072 bytes
    cudaFuncSetAttribute(chamfer_kernel,
                         cudaFuncAttributeMaxDynamicSharedMemorySize, smem);

    chamfer_kernel<<<BATCH * 2 * TILES, THREADS, smem>>>(x, y, out);
}